// round 5
// baseline (speedup 1.0000x reference)
#include <cuda_runtime.h>
#include <math.h>

#define N_NODES 40000
#define N_EDGES 640000
#define D 128
#define NLAYERS 3
#define BN_EPS 1e-5
#define GEMM_BM 32
#define GEMM_BLOCKS (N_NODES / GEMM_BM) /* 1250 */

// packed dual-fp32 FMA (sm_10x FFMA2): d = a*b + d elementwise on {lo,hi}
#define FMA_F32X2(d, a, b) \
    asm("fma.rn.f32x2 %0, %1, %2, %0;" : "+l"(d) : "l"(a), "l"(b))
#define UNPACK_F32X2(lo, hi, in) \
    asm("mov.b64 {%0, %1}, %2;" : "=r"(lo), "=r"(hi) : "l"(in))

// ---------------- scratch (__device__ globals; no allocations allowed) ----------------
__device__ int   g_deg[N_NODES];
__device__ int   g_cur[N_NODES];
__device__ int   g_offs[N_NODES + 1];
__device__ int   g_ssrc[N_EDGES];
__device__ float g_sew[N_EDGES];

__device__ float g_bufB[(size_t)N_NODES * D];  // y (GEMM1 out)
__device__ float g_bufZ[(size_t)N_NODES * D];  // z2 (GEMM2 out)

__device__ float g_psum[GEMM_BLOCKS * D];
__device__ float g_psq [GEMM_BLOCKS * D];
__device__ float g_a[D];
__device__ float g_c[D];

// ---------------- CSR build ----------------
__global__ void k_zero_deg() {
    int i = blockIdx.x * blockDim.x + threadIdx.x;
    if (i < N_NODES) g_deg[i] = 0;
}

__global__ void k_hist(const int* __restrict__ dst) {
    for (int e = blockIdx.x * blockDim.x + threadIdx.x; e < N_EDGES;
         e += gridDim.x * blockDim.x)
        atomicAdd(&g_deg[dst[e]], 1);
}

__global__ void k_scan() {
    __shared__ int sh[1024];
    int t = threadIdx.x;
    const int CH = (N_NODES + 1023) / 1024;  // 40
    int base = t * CH;
    int s = 0;
    for (int i = 0; i < CH; i++) {
        int idx = base + i;
        if (idx < N_NODES) s += g_deg[idx];
    }
    sh[t] = s;
    __syncthreads();
    for (int off = 1; off < 1024; off <<= 1) {
        int v = 0;
        if (t >= off) v = sh[t - off];
        __syncthreads();
        sh[t] += v;
        __syncthreads();
    }
    int run = (t == 0) ? 0 : sh[t - 1];
    for (int i = 0; i < CH; i++) {
        int idx = base + i;
        if (idx < N_NODES) {
            g_offs[idx] = run;
            run += g_deg[idx];
            g_cur[idx] = 0;
        }
    }
    if (t == 1023) g_offs[N_NODES] = run;
}

__global__ void k_scatter(const int* __restrict__ src, const int* __restrict__ dst,
                          const float* __restrict__ ew) {
    for (int e = blockIdx.x * blockDim.x + threadIdx.x; e < N_EDGES;
         e += gridDim.x * blockDim.x) {
        int d = dst[e];
        int p = g_offs[d] + atomicAdd(&g_cur[d], 1);
        g_ssrc[p] = src[e];
        g_sew[p]  = ew[e];
    }
}

// ---------------- fused GEMM (FFMA2): [stage X dup] -> 32x128 @ 128x128 -> epi -> stats
// Block: 32 rows x 128 cols, 256 threads, thread tile 4x4, accumulators in f32x2 pairs.
// smem: ws = W K-major [k][n] (64KB); xs2 = X tile with every element DUPLICATED
//       as a 64-bit {x,x} pair (64KB? no: 32*128*2 floats = 32KB). Total dyn 96KB.
// GATHER: X tile = (1+eps)*T(h[node]) + sum_e ew*T(h[src]); T = identity or
//         relu(g_a*v+g_c) when GPRO (BN2+ReLU of previous layer folded in).
// PRO:    X tile = relu(g_a*X + g_c) (BN1+ReLU folded into staging).
// RELUOUT: out = relu(acc + bias).
// Always: per-block column sum/sumsq -> g_psum/g_psq[blockIdx] (deterministic).
template <bool GATHER, bool GPRO, bool PRO, bool RELUOUT>
__global__ void __launch_bounds__(256, 2)
k_gemm(const float* __restrict__ X, const float* __restrict__ W,
       const float* __restrict__ bias,
       const float* __restrict__ epsl, int layer,
       float* __restrict__ Y) {
    extern __shared__ float sm[];
    float* ws  = sm;            // 128*128 floats
    float* xs2 = sm + D * D;    // 32*128 dup pairs = 8192 floats
    __shared__ float red[2][8][D];  // 8KB static, stats reduction

    int tid  = threadIdx.x;
    int wid  = tid >> 5;   // 0..7
    int lane = tid & 31;   // 0..31
    int row0 = blockIdx.x * GEMM_BM;

    // stage W
    const float4* W4 = (const float4*)W;
    float4* ws4 = (float4*)ws;
#pragma unroll 4
    for (int i = tid; i < D * D / 4; i += 256) ws4[i] = W4[i];

    // stage X (duplicated pairs)
    if (GATHER) {
        const float4* h4 = (const float4*)X;
        float ep = 1.f + epsl[layer];
        float4 ga, gc;
        if (GPRO) {
            ga = *(const float4*)(g_a + lane * 4);
            gc = *(const float4*)(g_c + lane * 4);
        }
        for (int i = wid; i < GEMM_BM; i += 8) {
            int node = row0 + i;
            int beg = g_offs[node], end = g_offs[node + 1];
            float4 a = make_float4(0.f, 0.f, 0.f, 0.f);
            int e = beg;
            for (; e + 3 < end; e += 4) {
                int   s0 = g_ssrc[e],     s1 = g_ssrc[e + 1];
                int   s2 = g_ssrc[e + 2], s3 = g_ssrc[e + 3];
                float w0 = g_sew[e],      w1 = g_sew[e + 1];
                float w2 = g_sew[e + 2],  w3 = g_sew[e + 3];
                float4 v0 = h4[(size_t)s0 * 32 + lane];
                float4 v1 = h4[(size_t)s1 * 32 + lane];
                float4 v2 = h4[(size_t)s2 * 32 + lane];
                float4 v3 = h4[(size_t)s3 * 32 + lane];
                if (GPRO) {
                    v0.x = fmaxf(fmaf(ga.x, v0.x, gc.x), 0.f); v0.y = fmaxf(fmaf(ga.y, v0.y, gc.y), 0.f);
                    v0.z = fmaxf(fmaf(ga.z, v0.z, gc.z), 0.f); v0.w = fmaxf(fmaf(ga.w, v0.w, gc.w), 0.f);
                    v1.x = fmaxf(fmaf(ga.x, v1.x, gc.x), 0.f); v1.y = fmaxf(fmaf(ga.y, v1.y, gc.y), 0.f);
                    v1.z = fmaxf(fmaf(ga.z, v1.z, gc.z), 0.f); v1.w = fmaxf(fmaf(ga.w, v1.w, gc.w), 0.f);
                    v2.x = fmaxf(fmaf(ga.x, v2.x, gc.x), 0.f); v2.y = fmaxf(fmaf(ga.y, v2.y, gc.y), 0.f);
                    v2.z = fmaxf(fmaf(ga.z, v2.z, gc.z), 0.f); v2.w = fmaxf(fmaf(ga.w, v2.w, gc.w), 0.f);
                    v3.x = fmaxf(fmaf(ga.x, v3.x, gc.x), 0.f); v3.y = fmaxf(fmaf(ga.y, v3.y, gc.y), 0.f);
                    v3.z = fmaxf(fmaf(ga.z, v3.z, gc.z), 0.f); v3.w = fmaxf(fmaf(ga.w, v3.w, gc.w), 0.f);
                }
                a.x = fmaf(w0, v0.x, a.x); a.y = fmaf(w0, v0.y, a.y);
                a.z = fmaf(w0, v0.z, a.z); a.w = fmaf(w0, v0.w, a.w);
                a.x = fmaf(w1, v1.x, a.x); a.y = fmaf(w1, v1.y, a.y);
                a.z = fmaf(w1, v1.z, a.z); a.w = fmaf(w1, v1.w, a.w);
                a.x = fmaf(w2, v2.x, a.x); a.y = fmaf(w2, v2.y, a.y);
                a.z = fmaf(w2, v2.z, a.z); a.w = fmaf(w2, v2.w, a.w);
                a.x = fmaf(w3, v3.x, a.x); a.y = fmaf(w3, v3.y, a.y);
                a.z = fmaf(w3, v3.z, a.z); a.w = fmaf(w3, v3.w, a.w);
            }
            for (; e < end; e++) {
                int s0 = g_ssrc[e];
                float w0 = g_sew[e];
                float4 v0 = h4[(size_t)s0 * 32 + lane];
                if (GPRO) {
                    v0.x = fmaxf(fmaf(ga.x, v0.x, gc.x), 0.f); v0.y = fmaxf(fmaf(ga.y, v0.y, gc.y), 0.f);
                    v0.z = fmaxf(fmaf(ga.z, v0.z, gc.z), 0.f); v0.w = fmaxf(fmaf(ga.w, v0.w, gc.w), 0.f);
                }
                a.x = fmaf(w0, v0.x, a.x); a.y = fmaf(w0, v0.y, a.y);
                a.z = fmaf(w0, v0.z, a.z); a.w = fmaf(w0, v0.w, a.w);
            }
            float4 sf = h4[(size_t)node * 32 + lane];
            if (GPRO) {
                sf.x = fmaxf(fmaf(ga.x, sf.x, gc.x), 0.f); sf.y = fmaxf(fmaf(ga.y, sf.y, gc.y), 0.f);
                sf.z = fmaxf(fmaf(ga.z, sf.z, gc.z), 0.f); sf.w = fmaxf(fmaf(ga.w, sf.w, gc.w), 0.f);
            }
            a.x = fmaf(ep, sf.x, a.x); a.y = fmaf(ep, sf.y, a.y);
            a.z = fmaf(ep, sf.z, a.z); a.w = fmaf(ep, sf.w, a.w);
            float* p = xs2 + (size_t)(i * D + lane * 4) * 2;
            *(float4*)(p)     = make_float4(a.x, a.x, a.y, a.y);
            *(float4*)(p + 4) = make_float4(a.z, a.z, a.w, a.w);
        }
    } else {
        const float4* X4 = (const float4*)(X + (size_t)row0 * D);
#pragma unroll
        for (int i = tid; i < GEMM_BM * D / 4; i += 256) {
            float4 v = X4[i];
            if (PRO) {
                int k = (i & 31) * 4;
                v.x = fmaxf(fmaf(g_a[k    ], v.x, g_c[k    ]), 0.f);
                v.y = fmaxf(fmaf(g_a[k + 1], v.y, g_c[k + 1]), 0.f);
                v.z = fmaxf(fmaf(g_a[k + 2], v.z, g_c[k + 2]), 0.f);
                v.w = fmaxf(fmaf(g_a[k + 3], v.w, g_c[k + 3]), 0.f);
            }
            int r = i >> 5, kq = i & 31;
            float* p = xs2 + (size_t)(r * D + kq * 4) * 2;
            *(float4*)(p)     = make_float4(v.x, v.x, v.y, v.y);
            *(float4*)(p + 4) = make_float4(v.z, v.z, v.w, v.w);
        }
    }
    __syncthreads();

    // ---- FFMA2 mainloop: 4 rows x 4 cols per thread ----
    int ty = wid;   // rows ty*4..+3 (warp-uniform -> A loads broadcast)
    int tx = lane;  // cols tx*4..+3 (B LDS.128 conflict-free)
    unsigned long long acc[4][2];
#pragma unroll
    for (int r = 0; r < 4; r++) { acc[r][0] = 0ull; acc[r][1] = 0ull; }

    const float* xr = xs2 + (size_t)(ty * 4) * D * 2;
#pragma unroll 4
    for (int k = 0; k < D; k += 4) {
        ulonglong2 b0 = *(const ulonglong2*)(ws + (k    ) * D + tx * 4);
        ulonglong2 b1 = *(const ulonglong2*)(ws + (k + 1) * D + tx * 4);
        ulonglong2 b2 = *(const ulonglong2*)(ws + (k + 2) * D + tx * 4);
        ulonglong2 b3 = *(const ulonglong2*)(ws + (k + 3) * D + tx * 4);
#pragma unroll
        for (int r = 0; r < 4; r++) {
            const float* ar = xr + (size_t)r * D * 2 + k * 2;
            ulonglong2 a01 = *(const ulonglong2*)(ar);      // {dup a_k, dup a_k+1}
            ulonglong2 a23 = *(const ulonglong2*)(ar + 4);  // {dup a_k+2, dup a_k+3}
            FMA_F32X2(acc[r][0], a01.x, b0.x); FMA_F32X2(acc[r][1], a01.x, b0.y);
            FMA_F32X2(acc[r][0], a01.y, b1.x); FMA_F32X2(acc[r][1], a01.y, b1.y);
            FMA_F32X2(acc[r][0], a23.x, b2.x); FMA_F32X2(acc[r][1], a23.x, b2.y);
            FMA_F32X2(acc[r][0], a23.y, b3.x); FMA_F32X2(acc[r][1], a23.y, b3.y);
        }
    }

    // ---- epilogue: unpack, bias (+relu), store, column stats ----
    float4 bb = *(const float4*)(bias + tx * 4);
    float s0 = 0.f, s1 = 0.f, s2 = 0.f, s3 = 0.f;
    float q0 = 0.f, q1 = 0.f, q2 = 0.f, q3 = 0.f;
#pragma unroll
    for (int r = 0; r < 4; r++) {
        unsigned int u0, u1, u2, u3;
        UNPACK_F32X2(u0, u1, acc[r][0]);
        UNPACK_F32X2(u2, u3, acc[r][1]);
        float4 o;
        o.x = __uint_as_float(u0) + bb.x; o.y = __uint_as_float(u1) + bb.y;
        o.z = __uint_as_float(u2) + bb.z; o.w = __uint_as_float(u3) + bb.w;
        if (RELUOUT) {
            o.x = fmaxf(o.x, 0.f); o.y = fmaxf(o.y, 0.f);
            o.z = fmaxf(o.z, 0.f); o.w = fmaxf(o.w, 0.f);
        }
        *(float4*)(Y + (size_t)(row0 + ty * 4 + r) * D + tx * 4) = o;
        s0 += o.x; s1 += o.y; s2 += o.z; s3 += o.w;
        q0 = fmaf(o.x, o.x, q0); q1 = fmaf(o.y, o.y, q1);
        q2 = fmaf(o.z, o.z, q2); q3 = fmaf(o.w, o.w, q3);
    }
    red[0][ty][tx * 4    ] = s0; red[0][ty][tx * 4 + 1] = s1;
    red[0][ty][tx * 4 + 2] = s2; red[0][ty][tx * 4 + 3] = s3;
    red[1][ty][tx * 4    ] = q0; red[1][ty][tx * 4 + 1] = q1;
    red[1][ty][tx * 4 + 2] = q2; red[1][ty][tx * 4 + 3] = q3;
    __syncthreads();
    if (tid < D) {
        float ps = 0.f, pq = 0.f;
#pragma unroll
        for (int j = 0; j < 8; j++) { ps += red[0][j][tid]; pq += red[1][j][tid]; }
        g_psum[blockIdx.x * D + tid] = ps;
        g_psq [blockIdx.x * D + tid] = pq;
    }
}

// ---------------- BN finalize: one block per feature column ----------------
__global__ void k_finalize(const float* __restrict__ gamma,
                           const float* __restrict__ beta) {
    __shared__ double sh[2][256];
    int c = blockIdx.x;    // 0..127
    int t = threadIdx.x;   // 256
    double s = 0.0, q = 0.0;
    for (int b = t; b < GEMM_BLOCKS; b += 256) {
        s += (double)g_psum[b * D + c];
        q += (double)g_psq [b * D + c];
    }
    sh[0][t] = s; sh[1][t] = q;
    __syncthreads();
    for (int o = 128; o > 0; o >>= 1) {
        if (t < o) { sh[0][t] += sh[0][t + o]; sh[1][t] += sh[1][t + o]; }
        __syncthreads();
    }
    if (t == 0) {
        double m   = sh[0][0] / (double)N_NODES;
        double var = sh[1][0] / (double)N_NODES - m * m;
        if (var < 0.0) var = 0.0;
        float inv = (float)(1.0 / sqrt(var + (double)BN_EPS));
        float a = gamma[c] * inv;
        g_a[c] = a;
        g_c[c] = beta[c] - a * (float)m;
    }
}

// ---------------- BN2 + ReLU elementwise (final layer only) ----------------
__global__ void k_bn_relu(const float* __restrict__ Z, float* __restrict__ O) {
    int i = blockIdx.x * blockDim.x + threadIdx.x;
    const int total = N_NODES * D / 4;
    if (i >= total) return;
    float4 v = ((const float4*)Z)[i];
    int k = (i & 31) * 4;
    float4 o;
    o.x = fmaxf(fmaf(g_a[k    ], v.x, g_c[k    ]), 0.f);
    o.y = fmaxf(fmaf(g_a[k + 1], v.y, g_c[k + 1]), 0.f);
    o.z = fmaxf(fmaf(g_a[k + 2], v.z, g_c[k + 2]), 0.f);
    o.w = fmaxf(fmaf(g_a[k + 3], v.w, g_c[k + 3]), 0.f);
    ((float4*)O)[i] = o;
}

// ---------------- launch ----------------
extern "C" void kernel_launch(void* const* d_in, const int* in_sizes, int n_in,
                              void* d_out, int out_size) {
    const float* h    = (const float*)d_in[0];
    const int*   src  = (const int*)d_in[1];
    const int*   dst  = (const int*)d_in[2];
    const float* ew   = (const float*)d_in[3];
    const float* epsl = (const float*)d_in[4];
    const float* W1   = (const float*)d_in[5];
    const float* b1   = (const float*)d_in[6];
    const float* g1   = (const float*)d_in[7];
    const float* bt1  = (const float*)d_in[8];
    const float* W2   = (const float*)d_in[9];
    const float* b2   = (const float*)d_in[10];
    const float* g2   = (const float*)d_in[11];
    const float* bt2  = (const float*)d_in[12];
    float* out = (float*)d_out;

    const size_t smem = (size_t)(D * D + GEMM_BM * D * 2) * sizeof(float);  // 98304 B
    cudaFuncSetAttribute(k_gemm<true, false, false, false>,
                         cudaFuncAttributeMaxDynamicSharedMemorySize, (int)smem);
    cudaFuncSetAttribute(k_gemm<true, true, false, false>,
                         cudaFuncAttributeMaxDynamicSharedMemorySize, (int)smem);
    cudaFuncSetAttribute(k_gemm<false, false, true, true>,
                         cudaFuncAttributeMaxDynamicSharedMemorySize, (int)smem);

    void *pB = nullptr, *pZ = nullptr;
    cudaGetSymbolAddress(&pB, g_bufB);
    cudaGetSymbolAddress(&pZ, g_bufZ);
    float* bufB = (float*)pB;
    float* bufZ = (float*)pZ;

    // CSR build (per replay; deterministic work)
    k_zero_deg<<<(N_NODES + 255) / 256, 256>>>();
    k_hist<<<640, 256>>>(dst);
    k_scan<<<1, 1024>>>();
    k_scatter<<<640, 256>>>(src, dst, ew);

    for (int l = 0; l < NLAYERS; l++) {
        // y = ((1+eps)*T(h) + sum ew*T(h[src])) @ W1 + b1   (+BN1 stats)
        // layer 0: T=identity from input h; layers 1,2: T=relu(bn2_prev(.)) from bufZ
        if (l == 0)
            k_gemm<true, false, false, false><<<GEMM_BLOCKS, 256, smem>>>(
                h, W1, b1, epsl, 0, bufB);
        else
            k_gemm<true, true, false, false><<<GEMM_BLOCKS, 256, smem>>>(
                bufZ, W1 + l * D * D, b1 + l * D, epsl, l, bufB);
        k_finalize<<<D, 256>>>(g1 + l * D, bt1 + l * D);
        // z2 = relu( relu(bn1(y)) @ W2 + b2 )   (+BN2 stats)
        k_gemm<false, false, true, true><<<GEMM_BLOCKS, 256, smem>>>(
            bufB, W2 + l * D * D, b2 + l * D, epsl, l, bufZ);
        k_finalize<<<D, 256>>>(g2 + l * D, bt2 + l * D);
        hin_unused:;
    }
    // final h = relu(bn2(z2)) -> out
    k_bn_relu<<<N_NODES * D / 4 / 256, 256>>>(bufZ, out);
}

// round 6
// speedup vs baseline: 1.1935x; 1.1935x over previous
#include <cuda_runtime.h>
#include <math.h>

#define N_NODES 40000
#define N_EDGES 640000
#define D 128
#define NLAYERS 3
#define BN_EPS 1e-5
#define GEMM_BM 64
#define GEMM_BLOCKS (N_NODES / GEMM_BM) /* 625 */

// packed dual-fp32 FMA (sm_10x FFMA2): d = a*b + d elementwise on {lo,hi}
#define FMA_F32X2(d, a, b) \
    asm("fma.rn.f32x2 %0, %1, %2, %0;" : "+l"(d) : "l"(a), "l"(b))
#define PACK_DUP_F32X2(out, f) \
    asm("mov.b64 %0, {%1, %1};" : "=l"(out) : "r"(__float_as_uint(f)))
#define UNPACK_F32X2(lo, hi, in) \
    asm("mov.b64 {%0, %1}, %2;" : "=r"(lo), "=r"(hi) : "l"(in))

// ---------------- scratch (__device__ globals; no allocations allowed) ----------------
__device__ int   g_deg[N_NODES];
__device__ int   g_cur[N_NODES];
__device__ int   g_offs[N_NODES + 1];
__device__ int   g_ssrc[N_EDGES];
__device__ float g_sew[N_EDGES];

__device__ float g_bufB[(size_t)N_NODES * D];  // y (GEMM1 out)
__device__ float g_bufZ[(size_t)N_NODES * D];  // z2 (GEMM2 out)

__device__ float g_psum[GEMM_BLOCKS * D];
__device__ float g_psq [GEMM_BLOCKS * D];
__device__ float g_a[D];
__device__ float g_c[D];

// ---------------- CSR build ----------------
__global__ void k_zero_deg() {
    int i = blockIdx.x * blockDim.x + threadIdx.x;
    if (i < N_NODES) g_deg[i] = 0;
}

__global__ void k_hist(const int* __restrict__ dst) {
    for (int e = blockIdx.x * blockDim.x + threadIdx.x; e < N_EDGES;
         e += gridDim.x * blockDim.x)
        atomicAdd(&g_deg[dst[e]], 1);
}

__global__ void k_scan() {
    __shared__ int sh[1024];
    int t = threadIdx.x;
    const int CH = (N_NODES + 1023) / 1024;  // 40
    int base = t * CH;
    int s = 0;
    for (int i = 0; i < CH; i++) {
        int idx = base + i;
        if (idx < N_NODES) s += g_deg[idx];
    }
    sh[t] = s;
    __syncthreads();
    for (int off = 1; off < 1024; off <<= 1) {
        int v = 0;
        if (t >= off) v = sh[t - off];
        __syncthreads();
        sh[t] += v;
        __syncthreads();
    }
    int run = (t == 0) ? 0 : sh[t - 1];
    for (int i = 0; i < CH; i++) {
        int idx = base + i;
        if (idx < N_NODES) {
            g_offs[idx] = run;
            run += g_deg[idx];
            g_cur[idx] = 0;
        }
    }
    if (t == 1023) g_offs[N_NODES] = run;
}

__global__ void k_scatter(const int* __restrict__ src, const int* __restrict__ dst,
                          const float* __restrict__ ew) {
    for (int e = blockIdx.x * blockDim.x + threadIdx.x; e < N_EDGES;
         e += gridDim.x * blockDim.x) {
        int d = dst[e];
        int p = g_offs[d] + atomicAdd(&g_cur[d], 1);
        g_ssrc[p] = src[e];
        g_sew[p]  = ew[e];
    }
}

// ---------------- fused GEMM: [stage X] -> 64x128 @ 128x128 -> [bias/ReLU] -> [stats]
// Block: 64 rows x 128 cols, 256 threads, thread tile 8x4 (accs as 8x2 f32x2 pairs).
// GATHER: X tile = (1+eps)*T(h[node]) + sum_e ew*T(h[src]); T = identity, or
//         relu(g_a*v+g_c) when GPRO (BN2+ReLU of previous layer folded into gather).
// PRO:    X tile = relu(g_a*X + g_c)  (BN1+ReLU folded into staging).
// RELUOUT: out = relu(acc + bias).
// Always: per-block column sum/sumsq -> g_psum/g_psq[blockIdx] (deterministic).
template <bool GATHER, bool GPRO, bool PRO, bool RELUOUT>
__global__ void k_gemm(const float* __restrict__ X, const float* __restrict__ W,
                       const float* __restrict__ bias,
                       const float* __restrict__ epsl, int layer,
                       float* __restrict__ Y) {
    extern __shared__ float sm[];
    float* ws = sm;             // 128*128 W (K-major [k][n]) 64KB
    float* xs = sm + D * D;     // 64*128 X tile 32KB
    __shared__ float red[2][8][D];  // static 8KB for stats reduction

    int tid  = threadIdx.x;
    int wid  = tid >> 5;   // 0..7
    int lane = tid & 31;   // 0..31
    int row0 = blockIdx.x * GEMM_BM;

    // stage W
    const float4* W4 = (const float4*)W;
    float4* ws4 = (float4*)ws;
#pragma unroll 4
    for (int i = tid; i < D * D / 4; i += 256) ws4[i] = W4[i];

    // stage X
    if (GATHER) {
        const float4* h4 = (const float4*)X;
        float ep = 1.f + epsl[layer];
        float4 ga, gc;
        if (GPRO) {
            ga = *(const float4*)(g_a + lane * 4);
            gc = *(const float4*)(g_c + lane * 4);
        }
        for (int i = wid; i < GEMM_BM; i += 8) {
            int node = row0 + i;
            int beg = g_offs[node], end = g_offs[node + 1];
            float4 a = make_float4(0.f, 0.f, 0.f, 0.f);
            int e = beg;
            for (; e + 1 < end; e += 2) {
                int   s0 = g_ssrc[e],  s1 = g_ssrc[e + 1];
                float w0 = g_sew[e],   w1 = g_sew[e + 1];
                float4 v0 = h4[(size_t)s0 * 32 + lane];
                float4 v1 = h4[(size_t)s1 * 32 + lane];
                if (GPRO) {
                    v0.x = fmaxf(fmaf(ga.x, v0.x, gc.x), 0.f); v0.y = fmaxf(fmaf(ga.y, v0.y, gc.y), 0.f);
                    v0.z = fmaxf(fmaf(ga.z, v0.z, gc.z), 0.f); v0.w = fmaxf(fmaf(ga.w, v0.w, gc.w), 0.f);
                    v1.x = fmaxf(fmaf(ga.x, v1.x, gc.x), 0.f); v1.y = fmaxf(fmaf(ga.y, v1.y, gc.y), 0.f);
                    v1.z = fmaxf(fmaf(ga.z, v1.z, gc.z), 0.f); v1.w = fmaxf(fmaf(ga.w, v1.w, gc.w), 0.f);
                }
                a.x = fmaf(w0, v0.x, a.x); a.y = fmaf(w0, v0.y, a.y);
                a.z = fmaf(w0, v0.z, a.z); a.w = fmaf(w0, v0.w, a.w);
                a.x = fmaf(w1, v1.x, a.x); a.y = fmaf(w1, v1.y, a.y);
                a.z = fmaf(w1, v1.z, a.z); a.w = fmaf(w1, v1.w, a.w);
            }
            if (e < end) {
                int s0 = g_ssrc[e];
                float w0 = g_sew[e];
                float4 v0 = h4[(size_t)s0 * 32 + lane];
                if (GPRO) {
                    v0.x = fmaxf(fmaf(ga.x, v0.x, gc.x), 0.f); v0.y = fmaxf(fmaf(ga.y, v0.y, gc.y), 0.f);
                    v0.z = fmaxf(fmaf(ga.z, v0.z, gc.z), 0.f); v0.w = fmaxf(fmaf(ga.w, v0.w, gc.w), 0.f);
                }
                a.x = fmaf(w0, v0.x, a.x); a.y = fmaf(w0, v0.y, a.y);
                a.z = fmaf(w0, v0.z, a.z); a.w = fmaf(w0, v0.w, a.w);
            }
            float4 sf = h4[(size_t)node * 32 + lane];
            if (GPRO) {
                sf.x = fmaxf(fmaf(ga.x, sf.x, gc.x), 0.f); sf.y = fmaxf(fmaf(ga.y, sf.y, gc.y), 0.f);
                sf.z = fmaxf(fmaf(ga.z, sf.z, gc.z), 0.f); sf.w = fmaxf(fmaf(ga.w, sf.w, gc.w), 0.f);
            }
            a.x = fmaf(ep, sf.x, a.x); a.y = fmaf(ep, sf.y, a.y);
            a.z = fmaf(ep, sf.z, a.z); a.w = fmaf(ep, sf.w, a.w);
            *(float4*)(xs + i * D + lane * 4) = a;
        }
    } else {
        const float4* X4 = (const float4*)(X + (size_t)row0 * D);
        float4* xs4 = (float4*)xs;
#pragma unroll
        for (int i = tid; i < GEMM_BM * D / 4; i += 256) {
            float4 v = X4[i];
            if (PRO) {
                int k = (i & 31) * 4;
                v.x = fmaxf(fmaf(g_a[k    ], v.x, g_c[k    ]), 0.f);
                v.y = fmaxf(fmaf(g_a[k + 1], v.y, g_c[k + 1]), 0.f);
                v.z = fmaxf(fmaf(g_a[k + 2], v.z, g_c[k + 2]), 0.f);
                v.w = fmaxf(fmaf(g_a[k + 3], v.w, g_c[k + 3]), 0.f);
            }
            xs4[i] = v;
        }
    }
    __syncthreads();

    // ---- mainloop: FFMA2 with register-broadcast A, natural W pairs ----
    int ty = wid;   // rows ty*8..+7 (warp-uniform -> A smem loads broadcast)
    int tx = lane;  // cols tx*4..+3 (B LDS.128 conflict-free)
    unsigned long long acc[8][2];
#pragma unroll
    for (int r = 0; r < 8; r++) { acc[r][0] = 0ull; acc[r][1] = 0ull; }

    const float* xr = xs + ty * 8 * D;
#pragma unroll 4
    for (int k = 0; k < D; k += 4) {
        ulonglong2 b0 = *(const ulonglong2*)(ws + (k    ) * D + tx * 4);
        ulonglong2 b1 = *(const ulonglong2*)(ws + (k + 1) * D + tx * 4);
        ulonglong2 b2 = *(const ulonglong2*)(ws + (k + 2) * D + tx * 4);
        ulonglong2 b3 = *(const ulonglong2*)(ws + (k + 3) * D + tx * 4);
#pragma unroll
        for (int r = 0; r < 8; r++) {
            float4 a = *(const float4*)(xr + r * D + k);
            unsigned long long px, py, pz, pw;
            PACK_DUP_F32X2(px, a.x);
            PACK_DUP_F32X2(py, a.y);
            PACK_DUP_F32X2(pz, a.z);
            PACK_DUP_F32X2(pw, a.w);
            FMA_F32X2(acc[r][0], px, b0.x); FMA_F32X2(acc[r][1], px, b0.y);
            FMA_F32X2(acc[r][0], py, b1.x); FMA_F32X2(acc[r][1], py, b1.y);
            FMA_F32X2(acc[r][0], pz, b2.x); FMA_F32X2(acc[r][1], pz, b2.y);
            FMA_F32X2(acc[r][0], pw, b3.x); FMA_F32X2(acc[r][1], pw, b3.y);
        }
    }

    // ---- epilogue: unpack, bias (+relu), store, column stats ----
    float4 bb = *(const float4*)(bias + tx * 4);
    float s0 = 0.f, s1 = 0.f, s2 = 0.f, s3 = 0.f;
    float q0 = 0.f, q1 = 0.f, q2 = 0.f, q3 = 0.f;
#pragma unroll
    for (int r = 0; r < 8; r++) {
        unsigned int u0, u1, u2, u3;
        UNPACK_F32X2(u0, u1, acc[r][0]);
        UNPACK_F32X2(u2, u3, acc[r][1]);
        float4 o;
        o.x = __uint_as_float(u0) + bb.x; o.y = __uint_as_float(u1) + bb.y;
        o.z = __uint_as_float(u2) + bb.z; o.w = __uint_as_float(u3) + bb.w;
        if (RELUOUT) {
            o.x = fmaxf(o.x, 0.f); o.y = fmaxf(o.y, 0.f);
            o.z = fmaxf(o.z, 0.f); o.w = fmaxf(o.w, 0.f);
        }
        *(float4*)(Y + (size_t)(row0 + ty * 8 + r) * D + tx * 4) = o;
        s0 += o.x; s1 += o.y; s2 += o.z; s3 += o.w;
        q0 = fmaf(o.x, o.x, q0); q1 = fmaf(o.y, o.y, q1);
        q2 = fmaf(o.z, o.z, q2); q3 = fmaf(o.w, o.w, q3);
    }
    red[0][ty][tx * 4    ] = s0; red[0][ty][tx * 4 + 1] = s1;
    red[0][ty][tx * 4 + 2] = s2; red[0][ty][tx * 4 + 3] = s3;
    red[1][ty][tx * 4    ] = q0; red[1][ty][tx * 4 + 1] = q1;
    red[1][ty][tx * 4 + 2] = q2; red[1][ty][tx * 4 + 3] = q3;
    __syncthreads();
    if (tid < D) {
        float ps = 0.f, pq = 0.f;
#pragma unroll
        for (int j = 0; j < 8; j++) { ps += red[0][j][tid]; pq += red[1][j][tid]; }
        g_psum[blockIdx.x * D + tid] = ps;
        g_psq [blockIdx.x * D + tid] = pq;
    }
}

// ---------------- BN finalize: one block per feature column ----------------
__global__ void k_finalize(const float* __restrict__ gamma,
                           const float* __restrict__ beta) {
    __shared__ double sh[2][256];
    int c = blockIdx.x;    // 0..127
    int t = threadIdx.x;   // 256
    double s = 0.0, q = 0.0;
    for (int b = t; b < GEMM_BLOCKS; b += 256) {
        s += (double)g_psum[b * D + c];
        q += (double)g_psq [b * D + c];
    }
    sh[0][t] = s; sh[1][t] = q;
    __syncthreads();
    for (int o = 128; o > 0; o >>= 1) {
        if (t < o) { sh[0][t] += sh[0][t + o]; sh[1][t] += sh[1][t + o]; }
        __syncthreads();
    }
    if (t == 0) {
        double m   = sh[0][0] / (double)N_NODES;
        double var = sh[1][0] / (double)N_NODES - m * m;
        if (var < 0.0) var = 0.0;
        float inv = (float)(1.0 / sqrt(var + (double)BN_EPS));
        float a = gamma[c] * inv;
        g_a[c] = a;
        g_c[c] = beta[c] - a * (float)m;
    }
}

// ---------------- BN2 + ReLU elementwise (final output only) ----------------
__global__ void k_bn_relu(const float* __restrict__ Z, float* __restrict__ O) {
    int i = blockIdx.x * blockDim.x + threadIdx.x;
    const int total = N_NODES * D / 4;
    if (i >= total) return;
    float4 v = ((const float4*)Z)[i];
    int k = (i & 31) * 4;
    float4 o;
    o.x = fmaxf(fmaf(g_a[k    ], v.x, g_c[k    ]), 0.f);
    o.y = fmaxf(fmaf(g_a[k + 1], v.y, g_c[k + 1]), 0.f);
    o.z = fmaxf(fmaf(g_a[k + 2], v.z, g_c[k + 2]), 0.f);
    o.w = fmaxf(fmaf(g_a[k + 3], v.w, g_c[k + 3]), 0.f);
    ((float4*)O)[i] = o;
}

// ---------------- launch ----------------
extern "C" void kernel_launch(void* const* d_in, const int* in_sizes, int n_in,
                              void* d_out, int out_size) {
    const float* h    = (const float*)d_in[0];
    const int*   src  = (const int*)d_in[1];
    const int*   dst  = (const int*)d_in[2];
    const float* ew   = (const float*)d_in[3];
    const float* epsl = (const float*)d_in[4];
    const float* W1   = (const float*)d_in[5];
    const float* b1   = (const float*)d_in[6];
    const float* g1   = (const float*)d_in[7];
    const float* bt1  = (const float*)d_in[8];
    const float* W2   = (const float*)d_in[9];
    const float* b2   = (const float*)d_in[10];
    const float* g2   = (const float*)d_in[11];
    const float* bt2  = (const float*)d_in[12];
    float* out = (float*)d_out;

    const size_t smem = (size_t)(D * D + GEMM_BM * D) * sizeof(float);  // 98304 B dyn
    cudaFuncSetAttribute(k_gemm<true, false, false, false>,
                         cudaFuncAttributeMaxDynamicSharedMemorySize, (int)smem);
    cudaFuncSetAttribute(k_gemm<true, true, false, false>,
                         cudaFuncAttributeMaxDynamicSharedMemorySize, (int)smem);
    cudaFuncSetAttribute(k_gemm<false, false, true, true>,
                         cudaFuncAttributeMaxDynamicSharedMemorySize, (int)smem);

    void *pB = nullptr, *pZ = nullptr;
    cudaGetSymbolAddress(&pB, g_bufB);
    cudaGetSymbolAddress(&pZ, g_bufZ);
    float* bufB = (float*)pB;
    float* bufZ = (float*)pZ;

    // CSR build (per replay; deterministic work)
    k_zero_deg<<<(N_NODES + 255) / 256, 256>>>();
    k_hist<<<640, 256>>>(dst);
    k_scan<<<1, 1024>>>();
    k_scatter<<<640, 256>>>(src, dst, ew);

    for (int l = 0; l < NLAYERS; l++) {
        // y = ((1+eps)*T(h) + sum ew*T(h[src])) @ W1 + b1   (+BN1 stats)
        // layer 0: T=identity from input h; layers 1,2: T=relu(bn2_prev(.)) on bufZ
        if (l == 0)
            k_gemm<true, false, false, false><<<GEMM_BLOCKS, 256, smem>>>(
                h, W1, b1, epsl, 0, bufB);
        else
            k_gemm<true, true, false, false><<<GEMM_BLOCKS, 256, smem>>>(
                bufZ, W1 + l * D * D, b1 + l * D, epsl, l, bufB);
        k_finalize<<<D, 256>>>(g1 + l * D, bt1 + l * D);
        // z2 = relu( relu(bn1(y)) @ W2 + b2 )   (+BN2 stats)
        k_gemm<false, false, true, true><<<GEMM_BLOCKS, 256, smem>>>(
            bufB, W2 + l * D * D, b2 + l * D, epsl, l, bufZ);
        k_finalize<<<D, 256>>>(g2 + l * D, bt2 + l * D);
    }
    // final h = relu(bn2(z2)) -> out
    k_bn_relu<<<N_NODES * D / 4 / 256, 256>>>(bufZ, out);
}

// round 8
// speedup vs baseline: 1.2924x; 1.0829x over previous
#include <cuda_runtime.h>
#include <cuda_bf16.h>
#include <math.h>

#define N_NODES 40000
#define N_EDGES 640000
#define D 128
#define NLAYERS 3
#define BN_EPS 1e-5
#define TC_BM 128
#define TC_BLOCKS ((N_NODES + TC_BM - 1) / TC_BM) /* 313 */
#define TC_THREADS 512
#define LDAB 272  /* padded row pitch in bytes: 136 bf16 */

typedef unsigned int uint;

__device__ __forceinline__ uint smem_to_u32(const void* p) {
    uint a;
    asm("{ .reg .u64 t; cvta.to.shared.u64 t, %1; cvt.u32.u64 %0, t; }"
        : "=r"(a) : "l"(p));
    return a;
}

#define LDSM_X4(r0, r1, r2, r3, addr) \
    asm volatile("ldmatrix.sync.aligned.m8n8.x4.shared.b16 {%0,%1,%2,%3}, [%4];" \
                 : "=r"(r0), "=r"(r1), "=r"(r2), "=r"(r3) : "r"(addr))
#define LDSM_X2(r0, r1, addr) \
    asm volatile("ldmatrix.sync.aligned.m8n8.x2.shared.b16 {%0,%1}, [%2];" \
                 : "=r"(r0), "=r"(r1) : "r"(addr))
#define MMA_BF16(d, a0, a1, a2, a3, b0, b1) \
    asm volatile("mma.sync.aligned.m16n8k16.row.col.f32.bf16.bf16.f32 " \
                 "{%0,%1,%2,%3}, {%4,%5,%6,%7}, {%8,%9}, {%0,%1,%2,%3};" \
                 : "+f"((d)[0]), "+f"((d)[1]), "+f"((d)[2]), "+f"((d)[3]) \
                 : "r"(a0), "r"(a1), "r"(a2), "r"(a3), "r"(b0), "r"(b1))

// split fp32 float4 -> bf16 hi/lo packed pairs
__device__ __forceinline__ void bsplit4(const float4& a, uint2& h, uint2& l) {
    __nv_bfloat16 hx = __float2bfloat16_rn(a.x);
    __nv_bfloat16 hy = __float2bfloat16_rn(a.y);
    __nv_bfloat16 hz = __float2bfloat16_rn(a.z);
    __nv_bfloat16 hw = __float2bfloat16_rn(a.w);
    __nv_bfloat16 lx = __float2bfloat16_rn(a.x - __bfloat162float(hx));
    __nv_bfloat16 ly = __float2bfloat16_rn(a.y - __bfloat162float(hy));
    __nv_bfloat16 lz = __float2bfloat16_rn(a.z - __bfloat162float(hz));
    __nv_bfloat16 lw = __float2bfloat16_rn(a.w - __bfloat162float(hw));
    h.x = (uint)__bfloat16_as_ushort(hx) | ((uint)__bfloat16_as_ushort(hy) << 16);
    h.y = (uint)__bfloat16_as_ushort(hz) | ((uint)__bfloat16_as_ushort(hw) << 16);
    l.x = (uint)__bfloat16_as_ushort(lx) | ((uint)__bfloat16_as_ushort(ly) << 16);
    l.y = (uint)__bfloat16_as_ushort(lz) | ((uint)__bfloat16_as_ushort(lw) << 16);
}

// ---------------- scratch ----------------
__device__ int   g_deg[N_NODES];
__device__ int   g_cur[N_NODES];
__device__ int   g_offs[N_NODES + 1];
__device__ int   g_ssrc[N_EDGES];
__device__ float g_sew[N_EDGES];

__device__ float g_bufB[(size_t)N_NODES * D];
__device__ float g_bufZ[(size_t)N_NODES * D];

__device__ __nv_bfloat16 g_wthi[6 * D * D];  // W^T hi, [mat][n][k] row-major
__device__ __nv_bfloat16 g_wtlo[6 * D * D];  // W^T lo

__device__ float g_psum[TC_BLOCKS * D];
__device__ float g_psq [TC_BLOCKS * D];
__device__ float g_a[D];
__device__ float g_c[D];

// ---------------- CSR build ----------------
__global__ void k_zero_deg() {
    int i = blockIdx.x * blockDim.x + threadIdx.x;
    if (i < N_NODES) g_deg[i] = 0;
}

__global__ void k_hist(const int* __restrict__ dst) {
    for (int e = blockIdx.x * blockDim.x + threadIdx.x; e < N_EDGES;
         e += gridDim.x * blockDim.x)
        atomicAdd(&g_deg[dst[e]], 1);
}

__global__ void k_scan() {
    __shared__ int sh[1024];
    int t = threadIdx.x;
    const int CH = (N_NODES + 1023) / 1024;
    int base = t * CH;
    int s = 0;
    for (int i = 0; i < CH; i++) {
        int idx = base + i;
        if (idx < N_NODES) s += g_deg[idx];
    }
    sh[t] = s;
    __syncthreads();
    for (int off = 1; off < 1024; off <<= 1) {
        int v = 0;
        if (t >= off) v = sh[t - off];
        __syncthreads();
        sh[t] += v;
        __syncthreads();
    }
    int run = (t == 0) ? 0 : sh[t - 1];
    for (int i = 0; i < CH; i++) {
        int idx = base + i;
        if (idx < N_NODES) {
            g_offs[idx] = run;
            run += g_deg[idx];
            g_cur[idx] = 0;
        }
    }
    if (t == 1023) g_offs[N_NODES] = run;
}

__global__ void k_scatter(const int* __restrict__ src, const int* __restrict__ dst,
                          const float* __restrict__ ew) {
    for (int e = blockIdx.x * blockDim.x + threadIdx.x; e < N_EDGES;
         e += gridDim.x * blockDim.x) {
        int d = dst[e];
        int p = g_offs[d] + atomicAdd(&g_cur[d], 1);
        g_ssrc[p] = src[e];
        g_sew[p]  = ew[e];
    }
}

// ---------------- W convert: transpose + bf16 split ----------------
__global__ void k_wconv(const float* __restrict__ W1, const float* __restrict__ W2) {
    extern __shared__ float ts[];  // [128][129]
    int m = blockIdx.x;
    int l = m >> 1;
    const float* src = (m & 1) ? (W2 + (size_t)l * D * D) : (W1 + (size_t)l * D * D);
    const float4* s4 = (const float4*)src;
    for (int e = threadIdx.x; e < D * D / 4; e += 256) {
        int k = e >> 5, n4 = e & 31;
        float4 v = s4[e];
        float* row = ts + k * 129 + n4 * 4;
        row[0] = v.x; row[1] = v.y; row[2] = v.z; row[3] = v.w;
    }
    __syncthreads();
    __nv_bfloat16* oh = g_wthi + (size_t)m * D * D;
    __nv_bfloat16* ol = g_wtlo + (size_t)m * D * D;
    for (int idx = threadIdx.x; idx < D * D / 8; idx += 256) {
        int n = idx >> 4, kg = idx & 15;
        uint uh[4], ul[4];
#pragma unroll
        for (int p = 0; p < 4; p++) {
            float f0 = ts[(kg * 8 + p * 2    ) * 129 + n];
            float f1 = ts[(kg * 8 + p * 2 + 1) * 129 + n];
            __nv_bfloat16 h0 = __float2bfloat16_rn(f0);
            __nv_bfloat16 h1 = __float2bfloat16_rn(f1);
            __nv_bfloat16 l0 = __float2bfloat16_rn(f0 - __bfloat162float(h0));
            __nv_bfloat16 l1 = __float2bfloat16_rn(f1 - __bfloat162float(h1));
            uh[p] = (uint)__bfloat16_as_ushort(h0) | ((uint)__bfloat16_as_ushort(h1) << 16);
            ul[p] = (uint)__bfloat16_as_ushort(l0) | ((uint)__bfloat16_as_ushort(l1) << 16);
        }
        ((uint4*)oh)[idx] = make_uint4(uh[0], uh[1], uh[2], uh[3]);
        ((uint4*)ol)[idx] = make_uint4(ul[0], ul[1], ul[2], ul[3]);
    }
}

// ---------------- tensor-core fused GEMM (mma.sync bf16-split) ----------------
// CTA: 128 rows x 128 cols, 512 threads (16 warps). Warp = (m-tile wid/2, n-half wid&1).
// A/B bf16 hi+lo in padded smem (row pitch 272B -> ldmatrix conflict-free).
// acc = Ah*Bh + Al*Bh + Ah*Bl (fp32), K=128 via 8 k-tiles of 16.
// GATHER: A = (1+eps)*T(h[node]) + sum ew*T(h[src]); T=relu(g_a*v+g_c) if GPRO.
// PRO: A = relu(g_a*X+g_c). RELUOUT: out = relu(acc + bias).
// Epilogue: bias/relu, store, butterfly-reduced deterministic column stats.
template <bool GATHER, bool GPRO, bool PRO, bool RELUOUT>
__global__ void __launch_bounds__(TC_THREADS, 1)
k_gemm_tc(const float* __restrict__ X, int wmat, const float* __restrict__ bias,
          const float* __restrict__ epsl, int layer, float* __restrict__ Y) {
    extern __shared__ char smp[];
    __shared__ float bias_s[D];
    __shared__ float red_s[16][D];
    __shared__ float red_q[16][D];

    const uint A_HI = 0, A_LO = 34816, B_HI = 69632, B_LO = 104448;

    int tid  = threadIdx.x;
    int wid  = tid >> 5;
    int lane = tid & 31;
    int row0 = blockIdx.x * TC_BM;

    uint sbase = smem_to_u32(smp);

    if (tid < D) bias_s[tid] = bias[tid];
    for (int i = tid; i < 16 * D; i += TC_THREADS) {
        ((float*)red_s)[i] = 0.f;
        ((float*)red_q)[i] = 0.f;
    }

    // ---- stage B (pre-split W^T, [n][k] row-major -> padded rows) ----
    {
        const uint4* bh4 = ((const uint4*)g_wthi) + (size_t)wmat * 2048;
        const uint4* bl4 = ((const uint4*)g_wtlo) + (size_t)wmat * 2048;
        for (int idx = tid; idx < 2048; idx += TC_THREADS) {
            int n = idx >> 4, kg = idx & 15;
            uint o = (uint)(n * LDAB + kg * 16);
            *(uint4*)(smp + B_HI + o) = bh4[idx];
            *(uint4*)(smp + B_LO + o) = bl4[idx];
        }
    }

    // ---- stage A (gather or load+PRO), split to bf16 hi/lo ----
    if (GATHER) {
        const float4* h4 = (const float4*)X;
        float ep = 1.f + epsl[layer];
        float4 ga, gc;
        if (GPRO) {
            ga = *(const float4*)(g_a + lane * 4);
            gc = *(const float4*)(g_c + lane * 4);
        }
        for (int i = wid; i < TC_BM; i += 16) {
            int node = row0 + i;
            float4 a = make_float4(0.f, 0.f, 0.f, 0.f);
            if (node < N_NODES) {
                int beg = g_offs[node], end = g_offs[node + 1];
                int e = beg;
                for (; e + 1 < end; e += 2) {
                    int   s0 = g_ssrc[e], s1 = g_ssrc[e + 1];
                    float w0 = g_sew[e],  w1 = g_sew[e + 1];
                    float4 v0 = h4[(size_t)s0 * 32 + lane];
                    float4 v1 = h4[(size_t)s1 * 32 + lane];
                    if (GPRO) {
                        v0.x = fmaxf(fmaf(ga.x, v0.x, gc.x), 0.f); v0.y = fmaxf(fmaf(ga.y, v0.y, gc.y), 0.f);
                        v0.z = fmaxf(fmaf(ga.z, v0.z, gc.z), 0.f); v0.w = fmaxf(fmaf(ga.w, v0.w, gc.w), 0.f);
                        v1.x = fmaxf(fmaf(ga.x, v1.x, gc.x), 0.f); v1.y = fmaxf(fmaf(ga.y, v1.y, gc.y), 0.f);
                        v1.z = fmaxf(fmaf(ga.z, v1.z, gc.z), 0.f); v1.w = fmaxf(fmaf(ga.w, v1.w, gc.w), 0.f);
                    }
                    a.x = fmaf(w0, v0.x, a.x); a.y = fmaf(w0, v0.y, a.y);
                    a.z = fmaf(w0, v0.z, a.z); a.w = fmaf(w0, v0.w, a.w);
                    a.x = fmaf(w1, v1.x, a.x); a.y = fmaf(w1, v1.y, a.y);
                    a.z = fmaf(w1, v1.z, a.z); a.w = fmaf(w1, v1.w, a.w);
                }
                if (e < end) {
                    int s0 = g_ssrc[e];
                    float w0 = g_sew[e];
                    float4 v0 = h4[(size_t)s0 * 32 + lane];
                    if (GPRO) {
                        v0.x = fmaxf(fmaf(ga.x, v0.x, gc.x), 0.f); v0.y = fmaxf(fmaf(ga.y, v0.y, gc.y), 0.f);
                        v0.z = fmaxf(fmaf(ga.z, v0.z, gc.z), 0.f); v0.w = fmaxf(fmaf(ga.w, v0.w, gc.w), 0.f);
                    }
                    a.x = fmaf(w0, v0.x, a.x); a.y = fmaf(w0, v0.y, a.y);
                    a.z = fmaf(w0, v0.z, a.z); a.w = fmaf(w0, v0.w, a.w);
                }
                float4 sf = h4[(size_t)node * 32 + lane];
                if (GPRO) {
                    sf.x = fmaxf(fmaf(ga.x, sf.x, gc.x), 0.f); sf.y = fmaxf(fmaf(ga.y, sf.y, gc.y), 0.f);
                    sf.z = fmaxf(fmaf(ga.z, sf.z, gc.z), 0.f); sf.w = fmaxf(fmaf(ga.w, sf.w, gc.w), 0.f);
                }
                a.x = fmaf(ep, sf.x, a.x); a.y = fmaf(ep, sf.y, a.y);
                a.z = fmaf(ep, sf.z, a.z); a.w = fmaf(ep, sf.w, a.w);
            }
            uint2 h2, l2;
            bsplit4(a, h2, l2);
            uint o = (uint)(i * LDAB + lane * 8);
            *(uint2*)(smp + A_HI + o) = h2;
            *(uint2*)(smp + A_LO + o) = l2;
        }
    } else {
        const float4* X4 = (const float4*)X;
        for (int i = wid; i < TC_BM; i += 16) {
            int node = row0 + i;
            float4 v = make_float4(0.f, 0.f, 0.f, 0.f);
            if (node < N_NODES) {
                v = X4[(size_t)node * 32 + lane];
                if (PRO) {
                    int k = lane * 4;
                    v.x = fmaxf(fmaf(g_a[k    ], v.x, g_c[k    ]), 0.f);
                    v.y = fmaxf(fmaf(g_a[k + 1], v.y, g_c[k + 1]), 0.f);
                    v.z = fmaxf(fmaf(g_a[k + 2], v.z, g_c[k + 2]), 0.f);
                    v.w = fmaxf(fmaf(g_a[k + 3], v.w, g_c[k + 3]), 0.f);
                }
            }
            uint2 h2, l2;
            bsplit4(v, h2, l2);
            uint o = (uint)(i * LDAB + lane * 8);
            *(uint2*)(smp + A_HI + o) = h2;
            *(uint2*)(smp + A_LO + o) = l2;
        }
    }
    __syncthreads();

    // ---- mma mainloop ----
    int mt = wid >> 1;          // m-tile: rows mt*16..+15
    int nh = (wid & 1) * 64;    // n-half: cols nh..nh+63 (8 n-tiles of 8)
    float acc[8][4];
#pragma unroll
    for (int j = 0; j < 8; j++)
#pragma unroll
        for (int c = 0; c < 4; c++) acc[j][c] = 0.f;

    // ldmatrix lane addresses
    uint aRowOff = (uint)((mt * 16 + (lane & 15)) * LDAB + ((lane >> 4) << 4));
    uint aHiAddr = sbase + A_HI + aRowOff;
    uint aLoAddr = sbase + A_LO + aRowOff;
    uint bRowOff = (uint)((nh + (lane & 7)) * LDAB + (((lane >> 3) & 1) << 4));
    uint bHiAddr = sbase + B_HI + bRowOff;
    uint bLoAddr = sbase + B_LO + bRowOff;

#pragma unroll
    for (int kt = 0; kt < 8; kt++) {
        uint ah0, ah1, ah2, ah3, al0, al1, al2, al3;
        LDSM_X4(ah0, ah1, ah2, ah3, aHiAddr + kt * 32);
        LDSM_X4(al0, al1, al2, al3, aLoAddr + kt * 32);
#pragma unroll
        for (int j = 0; j < 8; j++) {
            uint bh0, bh1, bl0, bl1;
            uint bo = (uint)(j * 8 * LDAB + kt * 32);
            LDSM_X2(bh0, bh1, bHiAddr + bo);
            LDSM_X2(bl0, bl1, bLoAddr + bo);
            MMA_BF16(acc[j], ah0, ah1, ah2, ah3, bh0, bh1);
            MMA_BF16(acc[j], al0, al1, al2, al3, bh0, bh1);
            MMA_BF16(acc[j], ah0, ah1, ah2, ah3, bl0, bl1);
        }
    }

    // ---- epilogue: bias/relu, store, column stats ----
    // d frag: {d0,d1} row lane>>2, cols c,c+1; {d2,d3} row+8
    int r0 = row0 + mt * 16 + (lane >> 2);
    int r1 = r0 + 8;
    bool v0 = r0 < N_NODES, v1 = r1 < N_NODES;
    float s[16], q[16];
#pragma unroll
    for (int j = 0; j < 8; j++) {
        int c = nh + j * 8 + (lane & 3) * 2;
        float o0 = acc[j][0] + bias_s[c];
        float o1 = acc[j][1] + bias_s[c + 1];
        float o2 = acc[j][2] + bias_s[c];
        float o3 = acc[j][3] + bias_s[c + 1];
        if (RELUOUT) {
            o0 = fmaxf(o0, 0.f); o1 = fmaxf(o1, 0.f);
            o2 = fmaxf(o2, 0.f); o3 = fmaxf(o3, 0.f);
        }
        if (!v0) { o0 = 0.f; o1 = 0.f; }
        if (!v1) { o2 = 0.f; o3 = 0.f; }
        if (v0) *(float2*)(Y + (size_t)r0 * D + c) = make_float2(o0, o1);
        if (v1) *(float2*)(Y + (size_t)r1 * D + c) = make_float2(o2, o3);
        s[j * 2    ] = o0 + o2;
        s[j * 2 + 1] = o1 + o3;
        q[j * 2    ] = fmaf(o0, o0, o2 * o2);
        q[j * 2 + 1] = fmaf(o1, o1, o3 * o3);
    }
    // butterfly over the 8 row-groups (lanes differing in bits 2..4)
#pragma unroll
    for (int off = 4; off <= 16; off <<= 1) {
#pragma unroll
        for (int i = 0; i < 16; i++) {
            s[i] += __shfl_xor_sync(0xFFFFFFFF, s[i], off);
            q[i] += __shfl_xor_sync(0xFFFFFFFF, q[i], off);
        }
    }
    if (lane < 4) {
#pragma unroll
        for (int j = 0; j < 8; j++) {
            int c = nh + j * 8 + lane * 2;
            red_s[wid][c    ] = s[j * 2    ];
            red_s[wid][c + 1] = s[j * 2 + 1];
            red_q[wid][c    ] = q[j * 2    ];
            red_q[wid][c + 1] = q[j * 2 + 1];
        }
    }
    __syncthreads();
    if (tid < D) {
        float ps = 0.f, pq = 0.f;
#pragma unroll
        for (int w = 0; w < 16; w++) { ps += red_s[w][tid]; pq += red_q[w][tid]; }
        g_psum[blockIdx.x * D + tid] = ps;
        g_psq [blockIdx.x * D + tid] = pq;
    }
}

// ---------------- BN finalize: one block per feature column ----------------
__global__ void k_finalize(const float* __restrict__ gamma,
                           const float* __restrict__ beta) {
    __shared__ double sh[2][256];
    int c = blockIdx.x;
    int t = threadIdx.x;
    double s = 0.0, q = 0.0;
    for (int b = t; b < TC_BLOCKS; b += 256) {
        s += (double)g_psum[b * D + c];
        q += (double)g_psq [b * D + c];
    }
    sh[0][t] = s; sh[1][t] = q;
    __syncthreads();
    for (int o = 128; o > 0; o >>= 1) {
        if (t < o) { sh[0][t] += sh[0][t + o]; sh[1][t] += sh[1][t + o]; }
        __syncthreads();
    }
    if (t == 0) {
        double m   = sh[0][0] / (double)N_NODES;
        double var = sh[1][0] / (double)N_NODES - m * m;
        if (var < 0.0) var = 0.0;
        float inv = (float)(1.0 / sqrt(var + (double)BN_EPS));
        float a = gamma[c] * inv;
        g_a[c] = a;
        g_c[c] = beta[c] - a * (float)m;
    }
}

// ---------------- BN2 + ReLU elementwise (final output) ----------------
__global__ void k_bn_relu(const float* __restrict__ Z, float* __restrict__ O) {
    int i = blockIdx.x * blockDim.x + threadIdx.x;
    const int total = N_NODES * D / 4;
    if (i >= total) return;
    float4 v = ((const float4*)Z)[i];
    int k = (i & 31) * 4;
    float4 o;
    o.x = fmaxf(fmaf(g_a[k    ], v.x, g_c[k    ]), 0.f);
    o.y = fmaxf(fmaf(g_a[k + 1], v.y, g_c[k + 1]), 0.f);
    o.z = fmaxf(fmaf(g_a[k + 2], v.z, g_c[k + 2]), 0.f);
    o.w = fmaxf(fmaf(g_a[k + 3], v.w, g_c[k + 3]), 0.f);
    ((float4*)O)[i] = o;
}

// ---------------- launch ----------------
extern "C" void kernel_launch(void* const* d_in, const int* in_sizes, int n_in,
                              void* d_out, int out_size) {
    const float* h    = (const float*)d_in[0];
    const int*   src  = (const int*)d_in[1];
    const int*   dst  = (const int*)d_in[2];
    const float* ew   = (const float*)d_in[3];
    const float* epsl = (const float*)d_in[4];
    const float* W1   = (const float*)d_in[5];
    const float* b1   = (const float*)d_in[6];
    const float* g1   = (const float*)d_in[7];
    const float* bt1  = (const float*)d_in[8];
    const float* W2   = (const float*)d_in[9];
    const float* b2   = (const float*)d_in[10];
    const float* g2   = (const float*)d_in[11];
    const float* bt2  = (const float*)d_in[12];
    float* out = (float*)d_out;

    const int tc_smem = 4 * 34816;  // 139264 B: A_hi, A_lo, B_hi, B_lo padded tiles
    cudaFuncSetAttribute(k_gemm_tc<true, false, false, false>,
                         cudaFuncAttributeMaxDynamicSharedMemorySize, tc_smem);
    cudaFuncSetAttribute(k_gemm_tc<true, true, false, false>,
                         cudaFuncAttributeMaxDynamicSharedMemorySize, tc_smem);
    cudaFuncSetAttribute(k_gemm_tc<false, false, true, true>,
                         cudaFuncAttributeMaxDynamicSharedMemorySize, tc_smem);
    const int wc_smem = 128 * 129 * 4;
    cudaFuncSetAttribute(k_wconv,
                         cudaFuncAttributeMaxDynamicSharedMemorySize, wc_smem);

    void *pB = nullptr, *pZ = nullptr;
    cudaGetSymbolAddress(&pB, g_bufB);
    cudaGetSymbolAddress(&pZ, g_bufZ);
    float* bufB = (float*)pB;
    float* bufZ = (float*)pZ;

    // CSR build + W transpose/split (per replay; deterministic)
    k_zero_deg<<<(N_NODES + 255) / 256, 256>>>();
    k_hist<<<640, 256>>>(dst);
    k_scan<<<1, 1024>>>();
    k_scatter<<<640, 256>>>(src, dst, ew);
    k_wconv<<<6, 256, wc_smem>>>(W1, W2);

    for (int l = 0; l < NLAYERS; l++) {
        // y = ((1+eps)*T(h) + sum ew*T(h[src])) @ W1 + b1   (+BN1 stats)
        if (l == 0)
            k_gemm_tc<true, false, false, false><<<TC_BLOCKS, TC_THREADS, tc_smem>>>(
                h, 0, b1, epsl, 0, bufB);
        else
            k_gemm_tc<true, true, false, false><<<TC_BLOCKS, TC_THREADS, tc_smem>>>(
                bufZ, l * 2, b1 + l * D, epsl, l, bufB);
        k_finalize<<<D, 256>>>(g1 + l * D, bt1 + l * D);
        // z2 = relu( relu(bn1(y)) @ W2 + b2 )   (+BN2 stats)
        k_gemm_tc<false, false, true, true><<<TC_BLOCKS, TC_THREADS, tc_smem>>>(
            bufB, l * 2 + 1, b2 + l * D, epsl, l, bufZ);
        k_finalize<<<D, 256>>>(g2 + l * D, bt2 + l * D);
    }
    // final h = relu(bn2(z2)) -> out
    k_bn_relu<<<N_NODES * D / 4 / 256, 256>>>(bufZ, out);
}

// round 12
// speedup vs baseline: 1.4918x; 1.1543x over previous
#include <cuda_runtime.h>
#include <cuda_bf16.h>
#include <math.h>

#define N_NODES 40000
#define N_EDGES 640000
#define D 128
#define NLAYERS 3
#define BN_EPS 1e-5
#define TC_BM 64
#define TC_BLOCKS ((N_NODES + TC_BM - 1) / TC_BM) /* 625 */
#define TC_THREADS 512
#define LDAB 272  /* padded row pitch in bytes: 136 bf16 */

typedef unsigned int uint;

__device__ __forceinline__ uint smem_to_u32(const void* p) {
    uint a;
    asm("{ .reg .u64 t; cvta.to.shared.u64 t, %1; cvt.u32.u64 %0, t; }"
        : "=r"(a) : "l"(p));
    return a;
}

#define LDSM_X4(r0, r1, r2, r3, addr) \
    asm volatile("ldmatrix.sync.aligned.m8n8.x4.shared.b16 {%0,%1,%2,%3}, [%4];" \
                 : "=r"(r0), "=r"(r1), "=r"(r2), "=r"(r3) : "r"(addr))
#define LDSM_X2(r0, r1, addr) \
    asm volatile("ldmatrix.sync.aligned.m8n8.x2.shared.b16 {%0,%1}, [%2];" \
                 : "=r"(r0), "=r"(r1) : "r"(addr))
#define MMA_BF16(d, a0, a1, a2, a3, b0, b1) \
    asm volatile("mma.sync.aligned.m16n8k16.row.col.f32.bf16.bf16.f32 " \
                 "{%0,%1,%2,%3}, {%4,%5,%6,%7}, {%8,%9}, {%0,%1,%2,%3};" \
                 : "+f"((d)[0]), "+f"((d)[1]), "+f"((d)[2]), "+f"((d)[3]) \
                 : "r"(a0), "r"(a1), "r"(a2), "r"(a3), "r"(b0), "r"(b1))

// split fp32 float4 -> bf16 hi/lo packed pairs
__device__ __forceinline__ void bsplit4(const float4& a, uint2& h, uint2& l) {
    __nv_bfloat16 hx = __float2bfloat16_rn(a.x);
    __nv_bfloat16 hy = __float2bfloat16_rn(a.y);
    __nv_bfloat16 hz = __float2bfloat16_rn(a.z);
    __nv_bfloat16 hw = __float2bfloat16_rn(a.w);
    __nv_bfloat16 lx = __float2bfloat16_rn(a.x - __bfloat162float(hx));
    __nv_bfloat16 ly = __float2bfloat16_rn(a.y - __bfloat162float(hy));
    __nv_bfloat16 lz = __float2bfloat16_rn(a.z - __bfloat162float(hz));
    __nv_bfloat16 lw = __float2bfloat16_rn(a.w - __bfloat162float(hw));
    h.x = (uint)__bfloat16_as_ushort(hx) | ((uint)__bfloat16_as_ushort(hy) << 16);
    h.y = (uint)__bfloat16_as_ushort(hz) | ((uint)__bfloat16_as_ushort(hw) << 16);
    l.x = (uint)__bfloat16_as_ushort(lx) | ((uint)__bfloat16_as_ushort(ly) << 16);
    l.y = (uint)__bfloat16_as_ushort(lz) | ((uint)__bfloat16_as_ushort(lw) << 16);
}

// ---------------- scratch ----------------
__device__ int   g_deg[N_NODES];
__device__ int   g_cur[N_NODES];
__device__ int   g_offs[N_NODES + 1];
__device__ int   g_ssrc[N_EDGES];
__device__ float g_sew[N_EDGES];

__device__ float g_bufB[(size_t)N_NODES * D];
__device__ float g_bufZ[(size_t)N_NODES * D];

__device__ __nv_bfloat16 g_wthi[6 * D * D];  // W^T hi, [mat][n][k] row-major
__device__ __nv_bfloat16 g_wtlo[6 * D * D];  // W^T lo

__device__ float g_psum[TC_BLOCKS * D];
__device__ float g_psq [TC_BLOCKS * D];
__device__ float g_a[D];
__device__ float g_c[D];

// ---------------- CSR build ----------------
__global__ void k_zero_deg() {
    int i = blockIdx.x * blockDim.x + threadIdx.x;
    if (i < N_NODES) g_deg[i] = 0;
}

__global__ void k_hist(const int* __restrict__ dst) {
    int e = blockIdx.x * blockDim.x + threadIdx.x;
    if (e < N_EDGES) atomicAdd(&g_deg[dst[e]], 1);
}

__global__ void k_scan() {
    __shared__ int sh[1024];
    int t = threadIdx.x;
    const int CH = (N_NODES + 1023) / 1024;
    int base = t * CH;
    int s = 0;
    for (int i = 0; i < CH; i++) {
        int idx = base + i;
        if (idx < N_NODES) s += g_deg[idx];
    }
    sh[t] = s;
    __syncthreads();
    for (int off = 1; off < 1024; off <<= 1) {
        int v = 0;
        if (t >= off) v = sh[t - off];
        __syncthreads();
        sh[t] += v;
        __syncthreads();
    }
    int run = (t == 0) ? 0 : sh[t - 1];
    for (int i = 0; i < CH; i++) {
        int idx = base + i;
        if (idx < N_NODES) {
            g_offs[idx] = run;
            run += g_deg[idx];
            g_cur[idx] = 0;
        }
    }
    if (t == 1023) g_offs[N_NODES] = run;
}

__global__ void k_scatter(const int* __restrict__ src, const int* __restrict__ dst,
                          const float* __restrict__ ew) {
    int e = blockIdx.x * blockDim.x + threadIdx.x;
    if (e >= N_EDGES) return;
    int d = dst[e];
    int p = g_offs[d] + atomicAdd(&g_cur[d], 1);
    g_ssrc[p] = src[e];
    g_sew[p]  = ew[e];
}

// ---------------- W convert: transpose + bf16 split ----------------
__global__ void k_wconv(const float* __restrict__ W1, const float* __restrict__ W2) {
    extern __shared__ float ts[];  // [128][129]
    int m = blockIdx.x;
    int l = m >> 1;
    const float* src = (m & 1) ? (W2 + (size_t)l * D * D) : (W1 + (size_t)l * D * D);
    const float4* s4 = (const float4*)src;
    for (int e = threadIdx.x; e < D * D / 4; e += 256) {
        int k = e >> 5, n4 = e & 31;
        float4 v = s4[e];
        float* row = ts + k * 129 + n4 * 4;
        row[0] = v.x; row[1] = v.y; row[2] = v.z; row[3] = v.w;
    }
    __syncthreads();
    __nv_bfloat16* oh = g_wthi + (size_t)m * D * D;
    __nv_bfloat16* ol = g_wtlo + (size_t)m * D * D;
    for (int idx = threadIdx.x; idx < D * D / 8; idx += 256) {
        int n = idx >> 4, kg = idx & 15;
        uint uh[4], ul[4];
#pragma unroll
        for (int p = 0; p < 4; p++) {
            float f0 = ts[(kg * 8 + p * 2    ) * 129 + n];
            float f1 = ts[(kg * 8 + p * 2 + 1) * 129 + n];
            __nv_bfloat16 h0 = __float2bfloat16_rn(f0);
            __nv_bfloat16 h1 = __float2bfloat16_rn(f1);
            __nv_bfloat16 l0 = __float2bfloat16_rn(f0 - __bfloat162float(h0));
            __nv_bfloat16 l1 = __float2bfloat16_rn(f1 - __bfloat162float(h1));
            uh[p] = (uint)__bfloat16_as_ushort(h0) | ((uint)__bfloat16_as_ushort(h1) << 16);
            ul[p] = (uint)__bfloat16_as_ushort(l0) | ((uint)__bfloat16_as_ushort(l1) << 16);
        }
        ((uint4*)oh)[idx] = make_uint4(uh[0], uh[1], uh[2], uh[3]);
        ((uint4*)ol)[idx] = make_uint4(ul[0], ul[1], ul[2], ul[3]);
    }
}

// ---------------- tensor-core fused GEMM (mma.sync bf16-split, BM=64, occ 2) ----------------
// CTA: 64 rows x 128 cols, 512 threads (16 warps = 4 m-tiles x 4 n-quarters).
// A/B bf16 hi+lo in padded smem (row pitch 272B -> ldmatrix conflict-free).
// acc = Ah*Bh + Al*Bh + Ah*Bl (fp32), K=128 via 8 k-tiles of 16.
// Stats scratch overlays the A-tile smem after the mainloop; each warp owns its
// 32-column quarter, and the final per-column sum reads ONLY the 4 owning warps
// (w = 4*mt + (c>>5)) in fixed order -> deterministic, no init required.
template <bool GATHER, bool GPRO, bool PRO, bool RELUOUT>
__global__ void __launch_bounds__(TC_THREADS, 2)
k_gemm_tc(const float* __restrict__ X, int wmat, const float* __restrict__ bias,
          const float* __restrict__ epsl, int layer, float* __restrict__ Y) {
    extern __shared__ char smp[];
    __shared__ float bias_s[D];

    const uint A_HI = 0, A_LO = 17408, B_HI = 34816, B_LO = 69632;
    // reduction scratch overlays the A region after the mainloop
    float* red_s = (float*)smp;             // [16][128]
    float* red_q = (float*)(smp + 8192);    // [16][128]

    int tid  = threadIdx.x;
    int wid  = tid >> 5;
    int lane = tid & 31;
    int row0 = blockIdx.x * TC_BM;

    uint sbase = smem_to_u32(smp);

    if (tid < D) bias_s[tid] = bias[tid];

    // ---- stage B (pre-split W^T, [n][k] row-major -> padded rows) ----
    {
        const uint4* bh4 = ((const uint4*)g_wthi) + (size_t)wmat * 2048;
        const uint4* bl4 = ((const uint4*)g_wtlo) + (size_t)wmat * 2048;
        for (int idx = tid; idx < 2048; idx += TC_THREADS) {
            int n = idx >> 4, kg = idx & 15;
            uint o = (uint)(n * LDAB + kg * 16);
            *(uint4*)(smp + B_HI + o) = bh4[idx];
            *(uint4*)(smp + B_LO + o) = bl4[idx];
        }
    }

    // ---- stage A (gather or load+PRO), split to bf16 hi/lo ----
    if (GATHER) {
        const float4* h4 = (const float4*)X;
        float ep = 1.f + epsl[layer];
        float4 ga, gc;
        if (GPRO) {
            ga = *(const float4*)(g_a + lane * 4);
            gc = *(const float4*)(g_c + lane * 4);
        }
        for (int i = wid; i < TC_BM; i += 16) {
            int node = row0 + i;
            float4 a = make_float4(0.f, 0.f, 0.f, 0.f);
            if (node < N_NODES) {
                int beg = g_offs[node], end = g_offs[node + 1];
                int e = beg;
                for (; e + 1 < end; e += 2) {
                    int   s0 = g_ssrc[e], s1 = g_ssrc[e + 1];
                    float w0 = g_sew[e],  w1 = g_sew[e + 1];
                    float4 v0 = h4[(size_t)s0 * 32 + lane];
                    float4 v1 = h4[(size_t)s1 * 32 + lane];
                    if (GPRO) {
                        v0.x = fmaxf(fmaf(ga.x, v0.x, gc.x), 0.f); v0.y = fmaxf(fmaf(ga.y, v0.y, gc.y), 0.f);
                        v0.z = fmaxf(fmaf(ga.z, v0.z, gc.z), 0.f); v0.w = fmaxf(fmaf(ga.w, v0.w, gc.w), 0.f);
                        v1.x = fmaxf(fmaf(ga.x, v1.x, gc.x), 0.f); v1.y = fmaxf(fmaf(ga.y, v1.y, gc.y), 0.f);
                        v1.z = fmaxf(fmaf(ga.z, v1.z, gc.z), 0.f); v1.w = fmaxf(fmaf(ga.w, v1.w, gc.w), 0.f);
                    }
                    a.x = fmaf(w0, v0.x, a.x); a.y = fmaf(w0, v0.y, a.y);
                    a.z = fmaf(w0, v0.z, a.z); a.w = fmaf(w0, v0.w, a.w);
                    a.x = fmaf(w1, v1.x, a.x); a.y = fmaf(w1, v1.y, a.y);
                    a.z = fmaf(w1, v1.z, a.z); a.w = fmaf(w1, v1.w, a.w);
                }
                if (e < end) {
                    int s0 = g_ssrc[e];
                    float w0 = g_sew[e];
                    float4 v0 = h4[(size_t)s0 * 32 + lane];
                    if (GPRO) {
                        v0.x = fmaxf(fmaf(ga.x, v0.x, gc.x), 0.f); v0.y = fmaxf(fmaf(ga.y, v0.y, gc.y), 0.f);
                        v0.z = fmaxf(fmaf(ga.z, v0.z, gc.z), 0.f); v0.w = fmaxf(fmaf(ga.w, v0.w, gc.w), 0.f);
                    }
                    a.x = fmaf(w0, v0.x, a.x); a.y = fmaf(w0, v0.y, a.y);
                    a.z = fmaf(w0, v0.z, a.z); a.w = fmaf(w0, v0.w, a.w);
                }
                float4 sf = h4[(size_t)node * 32 + lane];
                if (GPRO) {
                    sf.x = fmaxf(fmaf(ga.x, sf.x, gc.x), 0.f); sf.y = fmaxf(fmaf(ga.y, sf.y, gc.y), 0.f);
                    sf.z = fmaxf(fmaf(ga.z, sf.z, gc.z), 0.f); sf.w = fmaxf(fmaf(ga.w, sf.w, gc.w), 0.f);
                }
                a.x = fmaf(ep, sf.x, a.x); a.y = fmaf(ep, sf.y, a.y);
                a.z = fmaf(ep, sf.z, a.z); a.w = fmaf(ep, sf.w, a.w);
            }
            uint2 h2, l2;
            bsplit4(a, h2, l2);
            uint o = (uint)(i * LDAB + lane * 8);
            *(uint2*)(smp + A_HI + o) = h2;
            *(uint2*)(smp + A_LO + o) = l2;
        }
    } else {
        const float4* X4 = (const float4*)X;
        for (int i = wid; i < TC_BM; i += 16) {
            int node = row0 + i;
            float4 v = make_float4(0.f, 0.f, 0.f, 0.f);
            if (node < N_NODES) {
                v = X4[(size_t)node * 32 + lane];
                if (PRO) {
                    int k = lane * 4;
                    v.x = fmaxf(fmaf(g_a[k    ], v.x, g_c[k    ]), 0.f);
                    v.y = fmaxf(fmaf(g_a[k + 1], v.y, g_c[k + 1]), 0.f);
                    v.z = fmaxf(fmaf(g_a[k + 2], v.z, g_c[k + 2]), 0.f);
                    v.w = fmaxf(fmaf(g_a[k + 3], v.w, g_c[k + 3]), 0.f);
                }
            }
            uint2 h2, l2;
            bsplit4(v, h2, l2);
            uint o = (uint)(i * LDAB + lane * 8);
            *(uint2*)(smp + A_HI + o) = h2;
            *(uint2*)(smp + A_LO + o) = l2;
        }
    }
    __syncthreads();

    // ---- mma mainloop: warp = (m-tile mt rows mt*16.., n-quarter nq cols nq..nq+31) ----
    int mt = wid >> 2;
    int nq = (wid & 3) * 32;
    float acc[4][4];
#pragma unroll
    for (int j = 0; j < 4; j++)
#pragma unroll
        for (int c = 0; c < 4; c++) acc[j][c] = 0.f;

    uint aRowOff = (uint)((mt * 16 + (lane & 15)) * LDAB + ((lane >> 4) << 4));
    uint aHiAddr = sbase + A_HI + aRowOff;
    uint aLoAddr = sbase + A_LO + aRowOff;
    uint bRowOff = (uint)((nq + (lane & 7)) * LDAB + (((lane >> 3) & 1) << 4));
    uint bHiAddr = sbase + B_HI + bRowOff;
    uint bLoAddr = sbase + B_LO + bRowOff;

#pragma unroll
    for (int kt = 0; kt < 8; kt++) {
        uint ah0, ah1, ah2, ah3, al0, al1, al2, al3;
        LDSM_X4(ah0, ah1, ah2, ah3, aHiAddr + kt * 32);
        LDSM_X4(al0, al1, al2, al3, aLoAddr + kt * 32);
#pragma unroll
        for (int j = 0; j < 4; j++) {
            uint bh0, bh1, bl0, bl1;
            uint bo = (uint)(j * 8 * LDAB + kt * 32);
            LDSM_X2(bh0, bh1, bHiAddr + bo);
            LDSM_X2(bl0, bl1, bLoAddr + bo);
            MMA_BF16(acc[j], ah0, ah1, ah2, ah3, bh0, bh1);
            MMA_BF16(acc[j], al0, al1, al2, al3, bh0, bh1);
            MMA_BF16(acc[j], ah0, ah1, ah2, ah3, bl0, bl1);
        }
    }
    __syncthreads();  // all warps done reading A region -> safe to reuse for stats

    // ---- epilogue: bias/relu, store, column stats ----
    int r0 = row0 + mt * 16 + (lane >> 2);
    int r1 = r0 + 8;
    bool v0 = r0 < N_NODES, v1 = r1 < N_NODES;
    float s[8], q[8];
#pragma unroll
    for (int j = 0; j < 4; j++) {
        int c = nq + j * 8 + (lane & 3) * 2;
        float o0 = acc[j][0] + bias_s[c];
        float o1 = acc[j][1] + bias_s[c + 1];
        float o2 = acc[j][2] + bias_s[c];
        float o3 = acc[j][3] + bias_s[c + 1];
        if (RELUOUT) {
            o0 = fmaxf(o0, 0.f); o1 = fmaxf(o1, 0.f);
            o2 = fmaxf(o2, 0.f); o3 = fmaxf(o3, 0.f);
        }
        if (!v0) { o0 = 0.f; o1 = 0.f; }
        if (!v1) { o2 = 0.f; o3 = 0.f; }
        if (v0) *(float2*)(Y + (size_t)r0 * D + c) = make_float2(o0, o1);
        if (v1) *(float2*)(Y + (size_t)r1 * D + c) = make_float2(o2, o3);
        s[j * 2    ] = o0 + o2;
        s[j * 2 + 1] = o1 + o3;
        q[j * 2    ] = fmaf(o0, o0, o2 * o2);
        q[j * 2 + 1] = fmaf(o1, o1, o3 * o3);
    }
    // butterfly over the 8 row-groups (lane bits 2..4)
#pragma unroll
    for (int off = 4; off <= 16; off <<= 1) {
#pragma unroll
        for (int i = 0; i < 8; i++) {
            s[i] += __shfl_xor_sync(0xFFFFFFFF, s[i], off);
            q[i] += __shfl_xor_sync(0xFFFFFFFF, q[i], off);
        }
    }
    if (lane < 4) {
#pragma unroll
        for (int j = 0; j < 4; j++) {
            int c = nq + j * 8 + lane * 2;
            red_s[wid * D + c    ] = s[j * 2    ];
            red_s[wid * D + c + 1] = s[j * 2 + 1];
            red_q[wid * D + c    ] = q[j * 2    ];
            red_q[wid * D + c + 1] = q[j * 2 + 1];
        }
    }
    __syncthreads();
    if (tid < D) {
        // column tid is owned by warps w = 4*mt + (tid>>5); sum ONLY those 4
        int qsel = tid >> 5;
        float ps = 0.f, pq = 0.f;
#pragma unroll
        for (int m2 = 0; m2 < 4; m2++) {
            int w = m2 * 4 + qsel;
            ps += red_s[w * D + tid];
            pq += red_q[w * D + tid];
        }
        g_psum[blockIdx.x * D + tid] = ps;
        g_psq [blockIdx.x * D + tid] = pq;
    }
}

// ---------------- BN finalize: one block per feature column ----------------
__global__ void k_finalize(const float* __restrict__ gamma,
                           const float* __restrict__ beta) {
    __shared__ double sh[2][256];
    int c = blockIdx.x;
    int t = threadIdx.x;
    double s = 0.0, q = 0.0;
    for (int b = t; b < TC_BLOCKS; b += 256) {
        s += (double)g_psum[b * D + c];
        q += (double)g_psq [b * D + c];
    }
    sh[0][t] = s; sh[1][t] = q;
    __syncthreads();
    for (int o = 128; o > 0; o >>= 1) {
        if (t < o) { sh[0][t] += sh[0][t + o]; sh[1][t] += sh[1][t + o]; }
        __syncthreads();
    }
    if (t == 0) {
        double m   = sh[0][0] / (double)N_NODES;
        double var = sh[1][0] / (double)N_NODES - m * m;
        if (var < 0.0) var = 0.0;
        float inv = (float)(1.0 / sqrt(var + (double)BN_EPS));
        float a = gamma[c] * inv;
        g_a[c] = a;
        g_c[c] = beta[c] - a * (float)m;
    }
}

// ---------------- BN2 + ReLU elementwise (final output) ----------------
__global__ void k_bn_relu(const float* __restrict__ Z, float* __restrict__ O) {
    int i = blockIdx.x * blockDim.x + threadIdx.x;
    const int total = N_NODES * D / 4;
    if (i >= total) return;
    float4 v = ((const float4*)Z)[i];
    int k = (i & 31) * 4;
    float4 o;
    o.x = fmaxf(fmaf(g_a[k    ], v.x, g_c[k    ]), 0.f);
    o.y = fmaxf(fmaf(g_a[k + 1], v.y, g_c[k + 1]), 0.f);
    o.z = fmaxf(fmaf(g_a[k + 2], v.z, g_c[k + 2]), 0.f);
    o.w = fmaxf(fmaf(g_a[k + 3], v.w, g_c[k + 3]), 0.f);
    ((float4*)O)[i] = o;
}

// ---------------- launch ----------------
extern "C" void kernel_launch(void* const* d_in, const int* in_sizes, int n_in,
                              void* d_out, int out_size) {
    const float* h    = (const float*)d_in[0];
    const int*   src  = (const int*)d_in[1];
    const int*   dst  = (const int*)d_in[2];
    const float* ew   = (const float*)d_in[3];
    const float* epsl = (const float*)d_in[4];
    const float* W1   = (const float*)d_in[5];
    const float* b1   = (const float*)d_in[6];
    const float* g1   = (const float*)d_in[7];
    const float* bt1  = (const float*)d_in[8];
    const float* W2   = (const float*)d_in[9];
    const float* b2   = (const float*)d_in[10];
    const float* g2   = (const float*)d_in[11];
    const float* bt2  = (const float*)d_in[12];
    float* out = (float*)d_out;

    const int tc_smem = 104448;  // A_hi 17408 + A_lo 17408 + B_hi 34816 + B_lo 34816
    cudaFuncSetAttribute(k_gemm_tc<true, false, false, false>,
                         cudaFuncAttributeMaxDynamicSharedMemorySize, tc_smem);
    cudaFuncSetAttribute(k_gemm_tc<true, true, false, false>,
                         cudaFuncAttributeMaxDynamicSharedMemorySize, tc_smem);
    cudaFuncSetAttribute(k_gemm_tc<false, false, true, true>,
                         cudaFuncAttributeMaxDynamicSharedMemorySize, tc_smem);
    const int wc_smem = 128 * 129 * 4;
    cudaFuncSetAttribute(k_wconv,
                         cudaFuncAttributeMaxDynamicSharedMemorySize, wc_smem);

    void *pB = nullptr, *pZ = nullptr;
    cudaGetSymbolAddress(&pB, g_bufB);
    cudaGetSymbolAddress(&pZ, g_bufZ);
    float* bufB = (float*)pB;
    float* bufZ = (float*)pZ;

    // CSR build + W transpose/split (per replay; deterministic)
    k_zero_deg<<<(N_NODES + 255) / 256, 256>>>();
    k_hist<<<(N_EDGES + 255) / 256, 256>>>(dst);
    k_scan<<<1, 1024>>>();
    k_scatter<<<(N_EDGES + 255) / 256, 256>>>(src, dst, ew);
    k_wconv<<<6, 256, wc_smem>>>(W1, W2);

    for (int l = 0; l < NLAYERS; l++) {
        // y = ((1+eps)*T(h) + sum ew*T(h[src])) @ W1 + b1   (+BN1 stats)
        if (l == 0)
            k_gemm_tc<true, false, false, false><<<TC_BLOCKS, TC_THREADS, tc_smem>>>(
                h, 0, b1, epsl, 0, bufB);
        else
            k_gemm_tc<true, true, false, false><<<TC_BLOCKS, TC_THREADS, tc_smem>>>(
                bufZ, l * 2, b1 + l * D, epsl, l, bufB);
        k_finalize<<<D, 256>>>(g1 + l * D, bt1 + l * D);
        // z2 = relu( relu(bn1(y)) @ W2 + b2 )   (+BN2 stats)
        k_gemm_tc<false, false, true, true><<<TC_BLOCKS, TC_THREADS, tc_smem>>>(
            bufB, l * 2 + 1, b2 + l * D, epsl, l, bufZ);
        k_finalize<<<D, 256>>>(g2 + l * D, bt2 + l * D);
    }
    // final h = relu(bn2(z2)) -> out
    k_bn_relu<<<N_NODES * D / 4 / 256, 256>>>(bufZ, out);
}